// round 8
// baseline (speedup 1.0000x reference)
#include <cuda_runtime.h>
#include <cstdint>

#define BB 64
#define CC 64
#define HH 128
#define WW 128
#define NSLAB (BB * CC)
#define GRID1 148   // persistent, 1 CTA/SM (high-reg double-buffered), single wave

// Scratch (allocation-free rule: __device__ globals)
__device__ float g_cs_e [NSLAB * WW];   // colsum_e [b,c,w]  = sum_h exp(x-m)
__device__ float g_cs_ey[NSLAB * WW];   // colsum_ey[b,c,w]  = sum_h exp(x-m)*wy[h]

__device__ __forceinline__ void l2_prefetch_64k(const void* p) {
    asm volatile("cp.async.bulk.prefetch.L2.global [%0], %1;"
                 :: "l"(p), "r"(65536));
}

struct SM1 {
    float  smax[16];
    float4 se[16][32];
    float4 sy[16][32];
};

// Process one slab whose data sits in v[8] (consumed); bc = slab index.
__device__ __forceinline__ void process_slab(
    float4 (&v)[8], int bc, int tid, int wg, int hs, SM1* sm)
{
    const float inv127 = 1.0f / 127.0f;

    // ---- warp max, then CTA max (stalls on v's loads; next slab's loads
    //      were issued before this call and remain in flight) ----
    float m = v[0].x;
#pragma unroll
    for (int r = 0; r < 8; r++)
        m = fmaxf(m, fmaxf(fmaxf(v[r].x, v[r].y), fmaxf(v[r].z, v[r].w)));
#pragma unroll
    for (int o = 16; o; o >>= 1)
        m = fmaxf(m, __shfl_xor_sync(0xffffffffu, m, o));
    if (wg == 0) sm->smax[hs] = m;
    __syncthreads();                        // A (also fences se/sy reuse)
    float mc = sm->smax[0];
#pragma unroll
    for (int k = 1; k < 16; k++) mc = fmaxf(mc, sm->smax[k]);

    // ---- exp + per-thread column partial sums ----
    float ae0 = 0.f, ae1 = 0.f, ae2 = 0.f, ae3 = 0.f;
    float ay0 = 0.f, ay1 = 0.f, ay2 = 0.f, ay3 = 0.f;
#pragma unroll
    for (int r = 0; r < 8; r++) {
        const float wy = (float)(hs + 16 * r) * inv127;
        float e0 = __expf(v[r].x - mc);
        float e1 = __expf(v[r].y - mc);
        float e2 = __expf(v[r].z - mc);
        float e3 = __expf(v[r].w - mc);
        ae0 += e0; ay0 += e0 * wy;
        ae1 += e1; ay1 += e1 * wy;
        ae2 += e2; ay2 += e2 * wy;
        ae3 += e3; ay3 += e3 * wy;
    }

    // ---- deterministic combine over 16 warps ----
    sm->se[hs][wg] = make_float4(ae0, ae1, ae2, ae3);
    sm->sy[hs][wg] = make_float4(ay0, ay1, ay2, ay3);
    __syncthreads();                        // B

    if (tid < 128) {
        const float* p = reinterpret_cast<const float*>(sm->se);
        float s = 0.f;
#pragma unroll
        for (int k = 0; k < 16; k++) s += p[k * 128 + tid];
        g_cs_e[(size_t)bc * WW + tid] = s;
    } else if (tid < 256) {
        const int w = tid - 128;
        const float* p = reinterpret_cast<const float*>(sm->sy);
        float s = 0.f;
#pragma unroll
        for (int k = 0; k < 16; k++) s += p[k * 128 + w];
        g_cs_ey[(size_t)bc * WW + w] = s;
    }
}

// ---------------------------------------------------------------------------
// Pass 1 (persistent, register double-buffered):
//   grid=148 (1 CTA/SM), 512 threads = 16 warps x 32 lanes, 8 float4/thread
//   per buffer, two buffers (v0/v1). Loads for slab i+1 are issued at the
//   VERY TOP of iteration i (into the free buffer), so the memory pipe has
//   8 outstanding LDG.128/warp through max, barriers, exp and combine —
//   no per-CTA dead window in the DRAM stream.
// ---------------------------------------------------------------------------
__global__ __launch_bounds__(512, 1)
void sam_pass1(const float* __restrict__ x) {
    __shared__ SM1 sm;

    const int tid = threadIdx.x;
    const int wg  = tid & 31;
    const int hs  = tid >> 5;

    const float4* __restrict__ xp = reinterpret_cast<const float4*>(x);

    float4 v0[8], v1[8];

    int bc = blockIdx.x;
    if (bc < NSLAB) {
        if (tid == 0 && bc + GRID1 < NSLAB)
            l2_prefetch_64k(xp + (size_t)(bc + GRID1) * (HH * WW / 4));
        const float4* p = xp + (size_t)bc * (HH * WW / 4);
#pragma unroll
        for (int r = 0; r < 8; r++)
            v0[r] = p[(hs + 16 * r) * (WW / 4) + wg];
    }

    while (bc < NSLAB) {
        // -------- even half: compute v0, preload v1 --------
        {
            const int nbc = bc + GRID1;
            if (tid == 0 && nbc + GRID1 < NSLAB)
                l2_prefetch_64k(xp + (size_t)(nbc + GRID1) * (HH * WW / 4));
            if (nbc < NSLAB) {
                const float4* p = xp + (size_t)nbc * (HH * WW / 4);
#pragma unroll
                for (int r = 0; r < 8; r++)
                    v1[r] = p[(hs + 16 * r) * (WW / 4) + wg];
            }
            process_slab(v0, bc, tid, wg, hs, &sm);
            bc = nbc;
        }
        if (bc >= NSLAB) break;
        // -------- odd half: compute v1, preload v0 --------
        {
            const int nbc = bc + GRID1;
            if (tid == 0 && nbc + GRID1 < NSLAB)
                l2_prefetch_64k(xp + (size_t)(nbc + GRID1) * (HH * WW / 4));
            if (nbc < NSLAB) {
                const float4* p = xp + (size_t)nbc * (HH * WW / 4);
#pragma unroll
                for (int r = 0; r < 8; r++)
                    v0[r] = p[(hs + 16 * r) * (WW / 4) + wg];
            }
            process_slab(v1, bc, tid, wg, hs, &sm);
            bc = nbc;
        }
    }
}

// ---------------------------------------------------------------------------
// Pass 2: 2 CTAs per batch (grid=128), 512 threads. Each CTA redundantly
// computes rs[b,w] = 1 / sum_c colsum_e (L2-hot), then handles 32 channels.
// All global loads are issued before the first barrier. (Measured-best form.)
// ---------------------------------------------------------------------------
__global__ __launch_bounds__(512)
void sam_pass2(float* __restrict__ out) {
    const int b    = blockIdx.x >> 1;
    const int half = blockIdx.x & 1;
    const int tid  = threadIdx.x;

    const float* __restrict__ cse = g_cs_e  + (size_t)b * CC * WW;
    const float* __restrict__ csy = g_cs_ey + (size_t)b * CC * WW;

    __shared__ float sA[4][WW];
    __shared__ float rs[WW];

    const int w  = tid & 127;
    const int cg = tid >> 7;                    // 0..3
    float a[16];
#pragma unroll
    for (int k = 0; k < 16; k++)
        a[k] = cse[(cg + 4 * k) * WW + w];

    const int warp = tid >> 5;                  // 0..15
    const int lane = tid & 31;
    float pe[2][4], py[2][4];
#pragma unroll
    for (int i = 0; i < 2; i++) {
        const int c = half * 32 + warp * 2 + i;
#pragma unroll
        for (int j = 0; j < 4; j++) {
            const int ww = lane + 32 * j;
            pe[i][j] = cse[c * WW + ww];
            py[i][j] = csy[c * WW + ww];
        }
    }

    {
        float s = 0.f;
#pragma unroll
        for (int k = 0; k < 16; k++) s += a[k];
        sA[cg][w] = s;
    }
    __syncthreads();
    if (tid < WW) {
        rs[tid] = 1.0f / (sA[0][tid] + sA[1][tid] + sA[2][tid] + sA[3][tid]);
    }
    __syncthreads();

    const float inv127 = 1.0f / 127.0f;
#pragma unroll
    for (int i = 0; i < 2; i++) {
        const int c = half * 32 + warp * 2 + i;
        float xx = 0.f, xy = 0.f;
#pragma unroll
        for (int j = 0; j < 4; j++) {
            const int ww = lane + 32 * j;
            const float r = rs[ww];
            xx += pe[i][j] * ((float)ww * inv127) * r;
            xy += py[i][j] * r;
        }
#pragma unroll
        for (int o = 16; o; o >>= 1) {
            xx += __shfl_xor_sync(0xffffffffu, xx, o);
            xy += __shfl_xor_sync(0xffffffffu, xy, o);
        }
        if (lane == 0) {
            out[((size_t)b * CC + c) * 2 + 0] = xx;
            out[((size_t)b * CC + c) * 2 + 1] = xy;
        }
    }
}

extern "C" void kernel_launch(void* const* d_in, const int* in_sizes, int n_in,
                              void* d_out, int out_size) {
    const float* x = (const float*)d_in[0];
    float* out = (float*)d_out;
    sam_pass1<<<GRID1, 512>>>(x);
    sam_pass2<<<2 * BB, 512>>>(out);
}